// round 5
// baseline (speedup 1.0000x reference)
#include <cuda_runtime.h>
#include <cstdint>

#define Hh   64
#define Ww   176
#define HW   (Hh * Ww)
#define NCAM 2
#define NPIX (NCAM * HW)
#define Cc   128
#define Dd   80
#define Oo   208
#define TPV0 200
#define TPV1 704
#define TPV2 32
#define XY_CELLS (TPV0 * TPV1)
#define XZ_CELLS (TPV1 * TPV2)
#define YZ_CELLS (TPV0 * TPV2)

#define PC_MIN_X (-54.0f)
#define PC_MIN_Y (-54.0f)
#define PC_MIN_Z (-5.0f)
#define PROB_TH 1e-4f

#define XZ_SLOTS 28
#define YZ_SLOTS 32
#define KEY_XY 0x3FFFFu
#define KEY_XZ 0x7C03FFu
#define KEY_YZ 0x7FFC00u

__device__ float4 g_xy[XY_CELLS * 32];
__device__ float4 g_xz[XZ_CELLS * 32];
__device__ float4 g_yz[YZ_CELLS * 32];
__device__ float4 g_featv[NPIX * 32];
__device__ float4 g_probv[NPIX * 20];

__device__ __forceinline__ void red4(float* dst, float x, float y, float z, float w) {
    asm volatile("red.global.add.v4.f32 [%0], {%1,%2,%3,%4};"
                 :: "l"(dst), "f"(x), "f"(y), "f"(z), "f"(w) : "memory");
}

// ---- phase 1: per-pixel 208x128 GEMV + softmax(80); o-split over 2x128 threads ----
__global__ __launch_bounds__(256, 1)
void prep_kernel(const float* __restrict__ img,
                 const float* __restrict__ Wm,
                 const float* __restrict__ bias) {
    extern __shared__ float sm[];
    float* sW = sm;                 // 208*128
    float* sf = sm + Oo * Cc;       // 128*128, [c][px]
    const int tid = threadIdx.x;

    const float4* W4 = (const float4*)Wm;
    float4* sW4 = (float4*)sW;
    for (int i = tid; i < (Oo * Cc) / 4; i += 256) sW4[i] = W4[i];

    const int p0 = blockIdx.x * 128;
    for (int idx = tid; idx < 128 * Cc; idx += 256) {
        const int c = idx >> 7, px = idx & 127;
        const int p = p0 + px;
        const int n = p / HW, hw = p % HW;
        sf[c * 128 + px] = img[(size_t)n * Cc * HW + (size_t)c * HW + hw];
    }
    __syncthreads();

    const int px = tid & 127;
    const int p  = p0 + px;

    if (tid < 128) {
        // outputs 0..103: depth softmax + feature channels 0..23
        float lg[Dd];
        float m = -1e30f;
#pragma unroll 1
        for (int o = 0; o < Dd; o += 4) {
            float a0 = __ldg(&bias[o]), a1 = __ldg(&bias[o + 1]);
            float a2 = __ldg(&bias[o + 2]), a3 = __ldg(&bias[o + 3]);
            const float* w0 = sW + o * Cc;
#pragma unroll 8
            for (int c = 0; c < Cc; ++c) {
                float f = sf[c * 128 + px];
                a0 += w0[c] * f;
                a1 += w0[Cc + c] * f;
                a2 += w0[2 * Cc + c] * f;
                a3 += w0[3 * Cc + c] * f;
            }
            lg[o] = a0; lg[o + 1] = a1; lg[o + 2] = a2; lg[o + 3] = a3;
            m = fmaxf(m, fmaxf(fmaxf(a0, a1), fmaxf(a2, a3)));
        }
        float s = 0.f;
#pragma unroll 1
        for (int o = 0; o < Dd; ++o) { float e = expf(lg[o] - m); lg[o] = e; s += e; }
        const float inv = 1.0f / s;
        float4* probe = g_probv + (size_t)p * 20;
#pragma unroll 1
        for (int o = 0; o < Dd; o += 4) {
            float4 v;
            v.x = lg[o] * inv;     v.y = lg[o + 1] * inv;
            v.z = lg[o + 2] * inv; v.w = lg[o + 3] * inv;
            v.x = (v.x > PROB_TH) ? v.x : 0.f;
            v.y = (v.y > PROB_TH) ? v.y : 0.f;
            v.z = (v.z > PROB_TH) ? v.z : 0.f;
            v.w = (v.w > PROB_TH) ? v.w : 0.f;
            probe[o >> 2] = v;
        }
        float4* fout = g_featv + (size_t)p * 32;
#pragma unroll 1
        for (int o = Dd; o < 104; o += 4) {
            float a0 = __ldg(&bias[o]), a1 = __ldg(&bias[o + 1]);
            float a2 = __ldg(&bias[o + 2]), a3 = __ldg(&bias[o + 3]);
            const float* w0 = sW + o * Cc;
#pragma unroll 8
            for (int c = 0; c < Cc; ++c) {
                float f = sf[c * 128 + px];
                a0 += w0[c] * f;
                a1 += w0[Cc + c] * f;
                a2 += w0[2 * Cc + c] * f;
                a3 += w0[3 * Cc + c] * f;
            }
            fout[(o - Dd) >> 2] = make_float4(a0, a1, a2, a3);
        }
    } else {
        // outputs 104..207: feature channels 24..127
        float4* fout = g_featv + (size_t)p * 32;
#pragma unroll 1
        for (int o = 104; o < Oo; o += 4) {
            float a0 = __ldg(&bias[o]), a1 = __ldg(&bias[o + 1]);
            float a2 = __ldg(&bias[o + 2]), a3 = __ldg(&bias[o + 3]);
            const float* w0 = sW + o * Cc;
#pragma unroll 8
            for (int c = 0; c < Cc; ++c) {
                float f = sf[c * 128 + px];
                a0 += w0[c] * f;
                a1 += w0[Cc + c] * f;
                a2 += w0[2 * Cc + c] * f;
                a3 += w0[3 * Cc + c] * f;
            }
            fout[(o - Dd) >> 2] = make_float4(a0, a1, a2, a3);
        }
    }
}

__global__ void dummy_kernel() {}   // shifts scatter to launch #6 for ncu -s 5 -c 1

// ---- phase 2: column-block scatter with smem aggregation for xz/yz ----
// Block = one (cam, u) column of 64 rays. 8 warps: 0-3 xy RLE (16 rays each),
// 4-6 xz over d-thirds into warp-private slot arrays, 7 yz into slot array.
__global__ __launch_bounds__(256, 2)
void scatter_kernel(const float* __restrict__ intr,
                    const float* __restrict__ extr) {
    extern __shared__ unsigned char smraw[];
    float4*   accA  = (float4*)smraw;                          // xz 3*28*32 + yz 32*32
    unsigned* svox  = (unsigned*)(accA + (3 * XZ_SLOTS + YZ_SLOTS) * 32);  // 64*80
    float*    sprob = (float*)(svox + 64 * Dd);                // 64*80
    unsigned* stags = (unsigned*)(sprob + 64 * Dd);            // 3*28 + 32

    const int tid = threadIdx.x;
    const int col = blockIdx.x;          // 0..351
    const int n   = col / Ww;
    const int u   = col % Ww;

    // init accumulators + tags
    for (int i = tid; i < (3 * XZ_SLOTS + YZ_SLOTS) * 32; i += 256)
        accA[i] = make_float4(0.f, 0.f, 0.f, 0.f);
    for (int i = tid; i < 3 * XZ_SLOTS + YZ_SLOTS; i += 256)
        stags[i] = 0xFFFFFFFFu;

    // geometry constants (identical op chain to the passing kernel)
    const float* Kp = intr + n * 9;
    const float K00 = Kp[0], K02 = Kp[2];
    const float K11 = Kp[4], K12 = Kp[5];
    const float K22 = Kp[8];
    const float x22 = __fdiv_rn(1.0f, K22);
    const float k00 = __fdiv_rn(1.0f, K00);
    const float k11 = __fdiv_rn(1.0f, K11);
    const float k12 = __fdiv_rn(__fmul_rn(-K12, x22), K11);
    const float k02 = __fdiv_rn(__fmul_rn(-K02, x22), K00);
    const float uf = (float)u;
    const float rx = __fadd_rn(__fmul_rn(k00, uf), k02);
    const float rz = x22;
    const float* E = extr + n * 16;
    const float E0 = E[0], E1 = E[1], E2 = E[2],  E3 = E[3];
    const float E4 = E[4], E5 = E[5], E6 = E[6],  E7 = E[7];
    const float E8 = E[8], E9 = E[9], E10 = E[10], E11 = E[11];
    const float step   = 48.0f / 79.0f;
    const float RCP_XY = 1.0f / 0.54f;
    const float RCP_Z  = 4.0f;
    const float* gp = (const float*)g_probv;

    for (int i = tid; i < 64 * Dd; i += 256) {
        const int r = i / Dd, d = i % Dd;
        const float vf  = (float)r;
        const float ry  = __fadd_rn(__fmul_rn(k11, vf), k12);
        const float dsv = __fadd_rn(__fmul_rn(step, (float)d), 2.0f);
        const float cx = __fmul_rn(rx, dsv);
        const float cy = __fmul_rn(ry, dsv);
        const float cz = __fmul_rn(rz, dsv);
        const float wx = __fadd_rn(__fadd_rn(__fadd_rn(__fmul_rn(E0, cx),
                          __fmul_rn(E1, cy)), __fmul_rn(E2,  cz)), E3);
        const float wy = __fadd_rn(__fadd_rn(__fadd_rn(__fmul_rn(E4, cx),
                          __fmul_rn(E5, cy)), __fmul_rn(E6,  cz)), E7);
        const float wz = __fadd_rn(__fadd_rn(__fadd_rn(__fmul_rn(E8, cx),
                          __fmul_rn(E9, cy)), __fmul_rn(E10, cz)), E11);
        int vx = (int)__fmul_rn(__fsub_rn(wx, PC_MIN_X), RCP_XY);
        int vy = (int)__fmul_rn(__fsub_rn(wy, PC_MIN_Y), RCP_XY);
        int vz = (int)__fmul_rn(__fsub_rn(wz, PC_MIN_Z), RCP_Z);
        vx = min(max(vx, 0), TPV1 - 1);
        vy = min(max(vy, 0), TPV0 - 1);
        vz = min(max(vz, 0), TPV2 - 1);
        svox[i]  = (unsigned)vx | ((unsigned)vy << 10) | ((unsigned)vz << 18);
        const int p = n * HW + r * Ww + u;
        sprob[i] = gp[(size_t)p * Dd + d];
    }
    __syncthreads();

    const int wid  = tid >> 5;
    const int lane = tid & 31;

    if (wid < 4) {
        // ---- xy plane: per-ray RLE, direct red.v4 ----
#pragma unroll 1
        for (int rr = 0; rr < 16; ++rr) {
            const int r = wid * 16 + rr;
            const int p = n * HW + r * Ww + u;
            const float4 fv = g_featv[(size_t)p * 32 + lane];
            const unsigned* vox = svox + r * Dd;
            const float* pw = sprob + r * Dd;
            unsigned cur = vox[0] & KEY_XY;
            float acc = pw[0];
#pragma unroll 1
            for (int d = 1; d < Dd; ++d) {
                const unsigned k = vox[d] & KEY_XY;
                const float w = pw[d];
                if (k == cur) acc += w;
                else {
                    if (acc > 0.f) {
                        const unsigned vx = cur & 1023u, vy = cur >> 10;
                        float* dst = (float*)g_xy + ((size_t)(vy * TPV1 + vx) << 7) + (lane << 2);
                        red4(dst, fv.x * acc, fv.y * acc, fv.z * acc, fv.w * acc);
                    }
                    cur = k; acc = w;
                }
            }
            if (acc > 0.f) {
                const unsigned vx = cur & 1023u, vy = cur >> 10;
                float* dst = (float*)g_xy + ((size_t)(vy * TPV1 + vx) << 7) + (lane << 2);
                red4(dst, fv.x * acc, fv.y * acc, fv.z * acc, fv.w * acc);
            }
        }
    } else {
        // ---- xz (warps 4-6, d-thirds) and yz (warp 7) via smem slots ----
        const bool is_yz = (wid == 7);
        const int seg = wid - 4;
        const int d0 = is_yz ? 0  : (seg == 0 ? 0  : (seg == 1 ? 27 : 54));
        const int d1 = is_yz ? Dd : (seg == 0 ? 27 : (seg == 1 ? 54 : Dd));
        const int len = d1 - d0;
        const unsigned key_mask = is_yz ? KEY_YZ : KEY_XZ;
        const int nslots = is_yz ? YZ_SLOTS : XZ_SLOTS;
        float4*   acca = accA + (is_yz ? 3 * XZ_SLOTS * 32 : seg * XZ_SLOTS * 32);
        unsigned* taga = stags + (is_yz ? 3 * XZ_SLOTS : seg * XZ_SLOTS);
        float* gbase = is_yz ? (float*)g_yz : (float*)g_xz;

        // min/max of the slotted coordinate (vx for xz, vy for yz)
        unsigned mn = 0xFFFFu, mx = 0u;
        for (int i = lane; i < 64 * len; i += 32) {
            const int r = i / len, dd = d0 + i % len;
            const unsigned v = svox[r * Dd + dd];
            const unsigned cval = is_yz ? ((v >> 10) & 255u) : (v & 1023u);
            mn = min(mn, cval); mx = max(mx, cval);
        }
        mn = __reduce_min_sync(0xFFFFFFFFu, mn);
        mx = __reduce_max_sync(0xFFFFFFFFu, mx);
        const bool direct = (mx - mn) >= (unsigned)nslots;
        unsigned flags = 0;

#pragma unroll 1
        for (int r = 0; r < 64; ++r) {
            const int p = n * HW + r * Ww + u;
            const float4 fv = g_featv[(size_t)p * 32 + lane];
            const unsigned* vox = svox + r * Dd;
            const float* pw = sprob + r * Dd;
            unsigned cur = vox[d0] & key_mask;
            float acc = pw[d0];

            auto emit = [&](unsigned ckey, float cacc) {
                if (cacc <= 0.f) return;
                const unsigned vz = ckey >> 18;
                const unsigned cv = is_yz ? ((ckey >> 10) & 255u) : (ckey & 1023u);
                bool fallback = direct;
                if (!fallback) {
                    const unsigned slot = cv - mn;
                    unsigned t = taga[slot];
                    if (t == 0xFFFFFFFFu) { taga[slot] = vz; t = vz; }
                    if (t != vz) fallback = true;
                    else {
                        float4 a = acca[slot * 32 + lane];
                        a.x += fv.x * cacc; a.y += fv.y * cacc;
                        a.z += fv.z * cacc; a.w += fv.w * cacc;
                        acca[slot * 32 + lane] = a;
                        flags |= 1u << slot;
                    }
                }
                if (fallback) {
                    const unsigned cell = cv * TPV2 + vz;
                    red4(gbase + ((size_t)cell << 7) + (lane << 2),
                         fv.x * cacc, fv.y * cacc, fv.z * cacc, fv.w * cacc);
                }
            };

#pragma unroll 1
            for (int d = d0 + 1; d < d1; ++d) {
                const unsigned k = vox[d] & key_mask;
                const float w = pw[d];
                if (k == cur) acc += w;
                else { emit(cur, acc); cur = k; acc = w; }
            }
            emit(cur, acc);
        }

        if (!direct) {
#pragma unroll 1
            for (int s = 0; s < nslots; ++s) {
                if ((flags >> s) & 1u) {
                    const unsigned vz = taga[s];
                    const unsigned cell = (mn + s) * TPV2 + vz;
                    const float4 a = acca[s * 32 + lane];
                    red4(gbase + ((size_t)cell << 7) + (lane << 2), a.x, a.y, a.z, a.w);
                }
            }
        }
    }
}

// ---- phase 3: transpose [cell][C] -> [C][cell] ----
__global__ __launch_bounds__(256)
void transpose_kernel(const float* __restrict__ src, float* __restrict__ dst, int cells) {
    __shared__ float t[32][33];
    const int cell0 = blockIdx.x * 32;
    const int c0    = blockIdx.y * 32;
    const int tx = threadIdx.x, ty = threadIdx.y;
#pragma unroll
    for (int i = ty; i < 32; i += 8)
        t[i][tx] = src[(size_t)(cell0 + i) * Cc + c0 + tx];
    __syncthreads();
#pragma unroll
    for (int i = ty; i < 32; i += 8)
        dst[(size_t)(c0 + i) * cells + cell0 + tx] = t[tx][i];
}

extern "C" void kernel_launch(void* const* d_in, const int* in_sizes, int n_in,
                              void* d_out, int out_size) {
    const float* img  = (const float*)d_in[0];
    const float* intr = (const float*)d_in[2];
    const float* extr = (const float*)d_in[3];
    const float* Wm   = (const float*)d_in[4];
    const float* bias = (const float*)d_in[5];
    float* out = (float*)d_out;

    void *pxy, *pxz, *pyz;
    cudaGetSymbolAddress(&pxy, g_xy);
    cudaGetSymbolAddress(&pxz, g_xz);
    cudaGetSymbolAddress(&pyz, g_yz);
    cudaMemsetAsync(pxy, 0, sizeof(g_xy));
    cudaMemsetAsync(pxz, 0, sizeof(g_xz));
    cudaMemsetAsync(pyz, 0, sizeof(g_yz));

    const int prep_smem = (Oo * Cc + 128 * 128) * (int)sizeof(float);   // 168 KB
    cudaFuncSetAttribute(prep_kernel, cudaFuncAttributeMaxDynamicSharedMemorySize, prep_smem);
    prep_kernel<<<NPIX / 128, 256, prep_smem>>>(img, Wm, bias);

    dummy_kernel<<<1, 1>>>();

    const int sc_smem = (3 * XZ_SLOTS + YZ_SLOTS) * 32 * 16 + 64 * Dd * 8
                      + (3 * XZ_SLOTS + YZ_SLOTS) * 4;                  // ~100.8 KB
    cudaFuncSetAttribute(scatter_kernel, cudaFuncAttributeMaxDynamicSharedMemorySize, sc_smem);
    scatter_kernel<<<NCAM * Ww, 256, sc_smem>>>(intr, extr);

    dim3 tb(32, 8);
    transpose_kernel<<<dim3(XY_CELLS / 32, Cc / 32), tb>>>((const float*)pxy, out, XY_CELLS);
    transpose_kernel<<<dim3(XZ_CELLS / 32, Cc / 32), tb>>>((const float*)pxz,
                         out + (size_t)Cc * XY_CELLS, XZ_CELLS);
    transpose_kernel<<<dim3(YZ_CELLS / 32, Cc / 32), tb>>>((const float*)pyz,
                         out + (size_t)Cc * (XY_CELLS + XZ_CELLS), YZ_CELLS);
}

// round 6
// speedup vs baseline: 1.6392x; 1.6392x over previous
#include <cuda_runtime.h>
#include <cstdint>

#define Hh   64
#define Ww   176
#define HW   (Hh * Ww)
#define NCAM 2
#define NPIX (NCAM * HW)
#define Cc   128
#define Dd   80
#define Oo   208
#define TPV0 200
#define TPV1 704
#define TPV2 32
#define XY_CELLS (TPV0 * TPV1)
#define XZ_CELLS (TPV1 * TPV2)
#define YZ_CELLS (TPV0 * TPV2)

#define PC_MIN_X (-54.0f)
#define PC_MIN_Y (-54.0f)
#define PC_MIN_Z (-5.0f)
#define PROB_TH 1e-4f

#define PB 256            // pixels per prep block
#define WPAD 106          // padded sWt row stride (even -> 8B-aligned float2)

__device__ float4 g_xy[XY_CELLS * 32];
__device__ float4 g_xz[XZ_CELLS * 32];
__device__ float4 g_yz[YZ_CELLS * 32];
__device__ float4 g_featv[NPIX * 32];    // [pixel][128]
__device__ float4 g_probv[NPIX * 20];    // [pixel][80]
__device__ float  g_logit[NPIX * Dd];    // raw depth logits

__device__ __forceinline__ void red4(float* dst, float x, float y, float z, float w) {
    asm volatile("red.global.add.v4.f32 [%0], {%1,%2,%3,%4};"
                 :: "l"(dst), "f"(x), "f"(y), "f"(z), "f"(w) : "memory");
}

// ---- phase 1: GEMM 256px x 208 x 128, register tile 4px x 2out ----
// 256 threads: i = tid>>2 -> pixel group (4 consecutive px), j = tid&3 -> output
// quarter (26 outputs of the current 104-output half). Per c: one LDS.128 of
// features + one LDS.64 of transposed W per 8 FMA.
__global__ __launch_bounds__(256, 1)
void prep_kernel(const float* __restrict__ img,
                 const float* __restrict__ Wm,
                 const float* __restrict__ bias) {
    extern __shared__ float sm[];
    float* sf  = sm;                  // [c][256 px]  131 KB
    float* sWt = sm + Cc * PB;        // [c][WPAD]    54 KB (current output-half)

    const int tid = threadIdx.x;
    const int p0  = blockIdx.x * PB;
    const int n   = p0 / HW;
    const int hw0 = p0 % HW;

    // stage features once: coalesced global read, conflict-free smem write
    for (int idx = tid; idx < Cc * PB; idx += 256) {
        const int c = idx >> 8, px = idx & 255;
        sf[c * PB + px] = img[(size_t)n * Cc * HW + (size_t)c * HW + hw0 + px];
    }

    const int i = tid >> 2;           // 0..63
    const int j = tid & 3;            // 0..3

#pragma unroll 1
    for (int half = 0; half < 2; ++half) {
        const int obase = half * 104;
        __syncthreads();              // previous half's reads done before overwrite
        // stage W-half transposed: sWt[c][o] = Wm[obase+o][c]
        for (int idx = tid; idx < 104 * Cc; idx += 256) {
            const int o = idx >> 7, c = idx & 127;
            sWt[c * WPAD + o] = Wm[(size_t)(obase + o) * Cc + c];
        }
        __syncthreads();

#pragma unroll 1
        for (int g = 0; g < 13; ++g) {
            const int oo = j * 26 + g * 2;      // local output pair (even)
            float a00 = 0.f, a01 = 0.f, a10 = 0.f, a11 = 0.f;
            float a20 = 0.f, a21 = 0.f, a30 = 0.f, a31 = 0.f;
            const float* fp = sf + 4 * i;
            const float* wp = sWt + oo;
#pragma unroll 4
            for (int c = 0; c < Cc; ++c) {
                const float4 f = *(const float4*)(fp + c * PB);
                const float2 w = *(const float2*)(wp + c * WPAD);
                a00 += f.x * w.x; a01 += f.x * w.y;
                a10 += f.y * w.x; a11 += f.y * w.y;
                a20 += f.z * w.x; a21 += f.z * w.y;
                a30 += f.w * w.x; a31 += f.w * w.y;
            }
            const int o = obase + oo;
            const float b0 = __ldg(&bias[o]), b1 = __ldg(&bias[o + 1]);
            a00 += b0; a01 += b1; a10 += b0; a11 += b1;
            a20 += b0; a21 += b1; a30 += b0; a31 += b1;
            const int pbase = p0 + 4 * i;
            if (o < Dd) {              // depth logits (o, o+1 both < 80: oo pairs within quarter j=0..2, 26*3=78<80 ok; j=3 starts at 78: pair (78,79) ok)
                float2* dst = (float2*)(g_logit + (size_t)pbase * Dd + o);
                dst[0]                  = make_float2(a00, a01);
                *(float2*)((float*)dst + Dd)     = make_float2(a10, a11);
                *(float2*)((float*)dst + 2 * Dd) = make_float2(a20, a21);
                *(float2*)((float*)dst + 3 * Dd) = make_float2(a30, a31);
            } else {                   // feature channels
                float* fb = (float*)g_featv + (size_t)pbase * Cc + (o - Dd);
                *(float2*)fb            = make_float2(a00, a01);
                *(float2*)(fb + Cc)     = make_float2(a10, a11);
                *(float2*)(fb + 2 * Cc) = make_float2(a20, a21);
                *(float2*)(fb + 3 * Cc) = make_float2(a30, a31);
            }
        }
    }
}

// ---- phase 1b: softmax(80) + threshold, one warp per pixel ----
__global__ __launch_bounds__(256)
void softmax_kernel() {
    const int tid  = threadIdx.x;
    const int lane = tid & 31;
    const int p    = blockIdx.x * 8 + (tid >> 5);
    const float* lg = g_logit + (size_t)p * Dd;

    const float l0 = lg[lane];
    const float l1 = lg[lane + 32];
    const float l2 = (lane < 16) ? lg[lane + 64] : -1e30f;
    float m = fmaxf(l0, fmaxf(l1, l2));
#pragma unroll
    for (int s = 16; s; s >>= 1) m = fmaxf(m, __shfl_xor_sync(0xFFFFFFFFu, m, s));
    float e0 = expf(l0 - m), e1 = expf(l1 - m);
    float e2 = (lane < 16) ? expf(l2 - m) : 0.f;
    float s = e0 + e1 + e2;
#pragma unroll
    for (int sh = 16; sh; sh >>= 1) s += __shfl_xor_sync(0xFFFFFFFFu, s, sh);
    const float inv = 1.0f / s;
    float* pr = (float*)g_probv + (size_t)p * Dd;
    float v0 = e0 * inv, v1 = e1 * inv, v2 = e2 * inv;
    pr[lane]      = (v0 > PROB_TH) ? v0 : 0.f;
    pr[lane + 32] = (v1 > PROB_TH) ? v1 : 0.f;
    if (lane < 16) pr[lane + 64] = (v2 > PROB_TH) ? v2 : 0.f;
}

__global__ void dummy_kernel() {}

// ---- phase 2: per-pixel geometry + run-length aggregated v4 scatter (round-4) ----
__global__ __launch_bounds__(96, 8)
void scatter_kernel(const float* __restrict__ intr,
                    const float* __restrict__ extr) {
    __shared__ float4 sfeat[32];
    __shared__ float  spw[Dd];
    __shared__ int    sidx[3][Dd];

    const int p   = blockIdx.x;
    const int tid = threadIdx.x;

    if (tid < 32) sfeat[tid] = g_featv[(size_t)p * 32 + tid];

    if (tid < Dd) {
        spw[tid] = ((const float*)g_probv)[(size_t)p * Dd + tid];

        const int n  = p / HW;
        const int hw = p % HW;
        const int h  = hw / Ww;
        const int u  = hw % Ww;

        const float* Kp = intr + n * 9;
        const float K00 = Kp[0], K02 = Kp[2];
        const float K11 = Kp[4], K12 = Kp[5];
        const float K22 = Kp[8];
        const float x22 = __fdiv_rn(1.0f, K22);
        const float k00 = __fdiv_rn(1.0f, K00);
        const float k11 = __fdiv_rn(1.0f, K11);
        const float k12 = __fdiv_rn(__fmul_rn(-K12, x22), K11);
        const float k02 = __fdiv_rn(__fmul_rn(-K02, x22), K00);

        const float uf = (float)u, vf = (float)h;
        const float rx = __fadd_rn(__fmul_rn(k00, uf), k02);
        const float ry = __fadd_rn(__fmul_rn(k11, vf), k12);
        const float rz = x22;

        const float step = 48.0f / 79.0f;
        const float dsv = __fadd_rn(__fmul_rn(step, (float)tid), 2.0f);

        const float cx = __fmul_rn(rx, dsv);
        const float cy = __fmul_rn(ry, dsv);
        const float cz = __fmul_rn(rz, dsv);

        const float* E = extr + n * 16;
        const float wx = __fadd_rn(__fadd_rn(__fadd_rn(__fmul_rn(E[0], cx),
                         __fmul_rn(E[1], cy)), __fmul_rn(E[2],  cz)), E[3]);
        const float wy = __fadd_rn(__fadd_rn(__fadd_rn(__fmul_rn(E[4], cx),
                         __fmul_rn(E[5], cy)), __fmul_rn(E[6],  cz)), E[7]);
        const float wz = __fadd_rn(__fadd_rn(__fadd_rn(__fmul_rn(E[8], cx),
                         __fmul_rn(E[9], cy)), __fmul_rn(E[10], cz)), E[11]);

        const float RCP_XY = 1.0f / 0.54f;
        const float RCP_Z  = 4.0f;
        int vx = (int)__fmul_rn(__fsub_rn(wx, PC_MIN_X), RCP_XY);
        int vy = (int)__fmul_rn(__fsub_rn(wy, PC_MIN_Y), RCP_XY);
        int vz = (int)__fmul_rn(__fsub_rn(wz, PC_MIN_Z), RCP_Z);
        vx = min(max(vx, 0), TPV1 - 1);
        vy = min(max(vy, 0), TPV0 - 1);
        vz = min(max(vz, 0), TPV2 - 1);

        sidx[0][tid] = vy * TPV1 + vx;
        sidx[1][tid] = vx * TPV2 + vz;
        sidx[2][tid] = vy * TPV2 + vz;
    }
    __syncthreads();

    const int wid  = tid >> 5;
    const int lane = tid & 31;
    const float4 fv = sfeat[lane];
    float* base = (wid == 0) ? (float*)g_xy : (wid == 1) ? (float*)g_xz : (float*)g_yz;
    const int* idx = sidx[wid];

    int   cur = idx[0];
    float acc = spw[0];
#pragma unroll 1
    for (int d = 1; d < Dd; ++d) {
        const int   ix = idx[d];
        const float w  = spw[d];
        if (ix == cur) {
            acc += w;
        } else {
            if (acc > 0.f) {
                float* dst = base + ((size_t)cur << 7) + (lane << 2);
                red4(dst, fv.x * acc, fv.y * acc, fv.z * acc, fv.w * acc);
            }
            cur = ix;
            acc = w;
        }
    }
    if (acc > 0.f) {
        float* dst = base + ((size_t)cur << 7) + (lane << 2);
        red4(dst, fv.x * acc, fv.y * acc, fv.z * acc, fv.w * acc);
    }
}

// ---- phase 3: transpose [cell][C] -> [C][cell] ----
__global__ __launch_bounds__(256)
void transpose_kernel(const float* __restrict__ src, float* __restrict__ dst, int cells) {
    __shared__ float t[32][33];
    const int cell0 = blockIdx.x * 32;
    const int c0    = blockIdx.y * 32;
    const int tx = threadIdx.x, ty = threadIdx.y;
#pragma unroll
    for (int i = ty; i < 32; i += 8)
        t[i][tx] = src[(size_t)(cell0 + i) * Cc + c0 + tx];
    __syncthreads();
#pragma unroll
    for (int i = ty; i < 32; i += 8)
        dst[(size_t)(c0 + i) * cells + cell0 + tx] = t[tx][i];
}

extern "C" void kernel_launch(void* const* d_in, const int* in_sizes, int n_in,
                              void* d_out, int out_size) {
    const float* img  = (const float*)d_in[0];
    const float* intr = (const float*)d_in[2];
    const float* extr = (const float*)d_in[3];
    const float* Wm   = (const float*)d_in[4];
    const float* bias = (const float*)d_in[5];
    float* out = (float*)d_out;

    void *pxy, *pxz, *pyz;
    cudaGetSymbolAddress(&pxy, g_xy);
    cudaGetSymbolAddress(&pxz, g_xz);
    cudaGetSymbolAddress(&pyz, g_yz);
    cudaMemsetAsync(pxy, 0, sizeof(g_xy));
    cudaMemsetAsync(pxz, 0, sizeof(g_xz));
    cudaMemsetAsync(pyz, 0, sizeof(g_yz));

    const int prep_smem = (Cc * PB + Cc * WPAD) * (int)sizeof(float);   // ~185 KB
    cudaFuncSetAttribute(prep_kernel, cudaFuncAttributeMaxDynamicSharedMemorySize, prep_smem);
    prep_kernel<<<NPIX / PB, 256, prep_smem>>>(img, Wm, bias);

    softmax_kernel<<<NPIX / 8, 256>>>();
    dummy_kernel<<<1, 1>>>();          // -> scatter lands at ncu launch index 6

    scatter_kernel<<<NPIX, 96>>>(intr, extr);

    dim3 tb(32, 8);
    transpose_kernel<<<dim3(XY_CELLS / 32, Cc / 32), tb>>>((const float*)pxy, out, XY_CELLS);
    transpose_kernel<<<dim3(XZ_CELLS / 32, Cc / 32), tb>>>((const float*)pxz,
                         out + (size_t)Cc * XY_CELLS, XZ_CELLS);
    transpose_kernel<<<dim3(YZ_CELLS / 32, Cc / 32), tb>>>((const float*)pyz,
                         out + (size_t)Cc * (XY_CELLS + XZ_CELLS), YZ_CELLS);
}

// round 7
// speedup vs baseline: 1.6720x; 1.0200x over previous
#include <cuda_runtime.h>
#include <cstdint>

#define Hh   64
#define Ww   176
#define HW   (Hh * Ww)
#define NCAM 2
#define NPIX (NCAM * HW)
#define Cc   128
#define Dd   80
#define Oo   208
#define TPV0 200
#define TPV1 704
#define TPV2 32
#define XY_CELLS (TPV0 * TPV1)
#define XZ_CELLS (TPV1 * TPV2)
#define YZ_CELLS (TPV0 * TPV2)

#define PC_MIN_X (-54.0f)
#define PC_MIN_Y (-54.0f)
#define PC_MIN_Z (-5.0f)
#define PROB_TH 1e-4f

#define PB 256
#define WPAD 106

__device__ float4 g_xy[XY_CELLS * 32];
__device__ float4 g_xz[XZ_CELLS * 32];
__device__ float4 g_yz[YZ_CELLS * 32];
__device__ float4 g_featv[NPIX * 32];
__device__ float4 g_probv[NPIX * 20];
__device__ float  g_logit[NPIX * Dd];

__device__ __forceinline__ void red4(float* dst, float x, float y, float z, float w) {
    asm volatile("red.global.add.v4.f32 [%0], {%1,%2,%3,%4};"
                 :: "l"(dst), "f"(x), "f"(y), "f"(z), "f"(w) : "memory");
}

// ---- phase 1: GEMM 256px x 208 x 128, register tile 4px x 2out ----
__global__ __launch_bounds__(256, 1)
void prep_kernel(const float* __restrict__ img,
                 const float* __restrict__ Wm,
                 const float* __restrict__ bias) {
    extern __shared__ float sm[];
    float* sf  = sm;                  // [c][256 px]
    float* sWt = sm + Cc * PB;        // [c][WPAD]

    const int tid = threadIdx.x;
    const int p0  = blockIdx.x * PB;
    const int n   = p0 / HW;
    const int hw0 = p0 % HW;

    for (int idx = tid; idx < Cc * PB; idx += 256) {
        const int c = idx >> 8, px = idx & 255;
        sf[c * PB + px] = img[(size_t)n * Cc * HW + (size_t)c * HW + hw0 + px];
    }

    const int i = tid >> 2;
    const int j = tid & 3;

#pragma unroll 1
    for (int half = 0; half < 2; ++half) {
        const int obase = half * 104;
        __syncthreads();
        for (int idx = tid; idx < 104 * Cc; idx += 256) {
            const int o = idx >> 7, c = idx & 127;
            sWt[c * WPAD + o] = Wm[(size_t)(obase + o) * Cc + c];
        }
        __syncthreads();

#pragma unroll 1
        for (int g = 0; g < 13; ++g) {
            const int oo = j * 26 + g * 2;
            float a00 = 0.f, a01 = 0.f, a10 = 0.f, a11 = 0.f;
            float a20 = 0.f, a21 = 0.f, a30 = 0.f, a31 = 0.f;
            const float* fp = sf + 4 * i;
            const float* wp = sWt + oo;
#pragma unroll 4
            for (int c = 0; c < Cc; ++c) {
                const float4 f = *(const float4*)(fp + c * PB);
                const float2 w = *(const float2*)(wp + c * WPAD);
                a00 += f.x * w.x; a01 += f.x * w.y;
                a10 += f.y * w.x; a11 += f.y * w.y;
                a20 += f.z * w.x; a21 += f.z * w.y;
                a30 += f.w * w.x; a31 += f.w * w.y;
            }
            const int o = obase + oo;
            const float b0 = __ldg(&bias[o]), b1 = __ldg(&bias[o + 1]);
            a00 += b0; a01 += b1; a10 += b0; a11 += b1;
            a20 += b0; a21 += b1; a30 += b0; a31 += b1;
            const int pbase = p0 + 4 * i;
            if (o < Dd) {
                float2* dst = (float2*)(g_logit + (size_t)pbase * Dd + o);
                dst[0]                           = make_float2(a00, a01);
                *(float2*)((float*)dst + Dd)     = make_float2(a10, a11);
                *(float2*)((float*)dst + 2 * Dd) = make_float2(a20, a21);
                *(float2*)((float*)dst + 3 * Dd) = make_float2(a30, a31);
            } else {
                float* fb = (float*)g_featv + (size_t)pbase * Cc + (o - Dd);
                *(float2*)fb            = make_float2(a00, a01);
                *(float2*)(fb + Cc)     = make_float2(a10, a11);
                *(float2*)(fb + 2 * Cc) = make_float2(a20, a21);
                *(float2*)(fb + 3 * Cc) = make_float2(a30, a31);
            }
        }
    }
}

// ---- phase 1b: softmax(80), one warp per pixel ----
__global__ __launch_bounds__(256)
void softmax_kernel() {
    const int tid  = threadIdx.x;
    const int lane = tid & 31;
    const int p    = blockIdx.x * 8 + (tid >> 5);
    const float* lg = g_logit + (size_t)p * Dd;

    const float l0 = lg[lane];
    const float l1 = lg[lane + 32];
    const float l2 = (lane < 16) ? lg[lane + 64] : -1e30f;
    float m = fmaxf(l0, fmaxf(l1, l2));
#pragma unroll
    for (int s = 16; s; s >>= 1) m = fmaxf(m, __shfl_xor_sync(0xFFFFFFFFu, m, s));
    float e0 = expf(l0 - m), e1 = expf(l1 - m);
    float e2 = (lane < 16) ? expf(l2 - m) : 0.f;
    float s = e0 + e1 + e2;
#pragma unroll
    for (int sh = 16; sh; sh >>= 1) s += __shfl_xor_sync(0xFFFFFFFFu, s, sh);
    const float inv = 1.0f / s;
    float* pr = (float*)g_probv + (size_t)p * Dd;
    float v0 = e0 * inv, v1 = e1 * inv, v2 = e2 * inv;
    pr[lane]      = (v0 > PROB_TH) ? v0 : 0.f;
    pr[lane + 32] = (v1 > PROB_TH) ? v1 : 0.f;
    if (lane < 16) pr[lane + 64] = (v2 > PROB_TH) ? v2 : 0.f;
}

__global__ void dummy_kernel() {}

// ---- phase 2: 6-warp scatter (2 warps per plane, 40 depths each) ----
__global__ __launch_bounds__(192, 8)
void scatter_kernel(const float* __restrict__ intr,
                    const float* __restrict__ extr) {
    __shared__ float4 sfeat[32];
    __shared__ int2   spr[3][Dd];     // (cell, w-bits) per plane per depth

    const int p   = blockIdx.x;
    const int tid = threadIdx.x;

    if (tid < 32) sfeat[tid] = g_featv[(size_t)p * 32 + tid];

    if (tid < Dd) {
        const float w = ((const float*)g_probv)[(size_t)p * Dd + tid];
        const int wb  = __float_as_int(w);

        const int n  = p / HW;
        const int hw = p % HW;
        const int h  = hw / Ww;
        const int u  = hw % Ww;

        const float* Kp = intr + n * 9;
        const float K00 = Kp[0], K02 = Kp[2];
        const float K11 = Kp[4], K12 = Kp[5];
        const float K22 = Kp[8];
        const float x22 = __fdiv_rn(1.0f, K22);
        const float k00 = __fdiv_rn(1.0f, K00);
        const float k11 = __fdiv_rn(1.0f, K11);
        const float k12 = __fdiv_rn(__fmul_rn(-K12, x22), K11);
        const float k02 = __fdiv_rn(__fmul_rn(-K02, x22), K00);

        const float uf = (float)u, vf = (float)h;
        const float rx = __fadd_rn(__fmul_rn(k00, uf), k02);
        const float ry = __fadd_rn(__fmul_rn(k11, vf), k12);
        const float rz = x22;

        const float step = 48.0f / 79.0f;
        const float dsv = __fadd_rn(__fmul_rn(step, (float)tid), 2.0f);

        const float cx = __fmul_rn(rx, dsv);
        const float cy = __fmul_rn(ry, dsv);
        const float cz = __fmul_rn(rz, dsv);

        const float* E = extr + n * 16;
        const float wx = __fadd_rn(__fadd_rn(__fadd_rn(__fmul_rn(E[0], cx),
                         __fmul_rn(E[1], cy)), __fmul_rn(E[2],  cz)), E[3]);
        const float wy = __fadd_rn(__fadd_rn(__fadd_rn(__fmul_rn(E[4], cx),
                         __fmul_rn(E[5], cy)), __fmul_rn(E[6],  cz)), E[7]);
        const float wz = __fadd_rn(__fadd_rn(__fadd_rn(__fmul_rn(E[8], cx),
                         __fmul_rn(E[9], cy)), __fmul_rn(E[10], cz)), E[11]);

        const float RCP_XY = 1.0f / 0.54f;
        const float RCP_Z  = 4.0f;
        int vx = (int)__fmul_rn(__fsub_rn(wx, PC_MIN_X), RCP_XY);
        int vy = (int)__fmul_rn(__fsub_rn(wy, PC_MIN_Y), RCP_XY);
        int vz = (int)__fmul_rn(__fsub_rn(wz, PC_MIN_Z), RCP_Z);
        vx = min(max(vx, 0), TPV1 - 1);
        vy = min(max(vy, 0), TPV0 - 1);
        vz = min(max(vz, 0), TPV2 - 1);

        spr[0][tid] = make_int2(vy * TPV1 + vx, wb);
        spr[1][tid] = make_int2(vx * TPV2 + vz, wb);
        spr[2][tid] = make_int2(vy * TPV2 + vz, wb);
    }
    __syncthreads();

    const int wrp   = tid >> 5;
    const int lane  = tid & 31;
    const int plane = wrp >> 1;       // 0,1,2
    const int d0    = (wrp & 1) * 40;
    const int d1    = d0 + 40;
    const float4 fv = sfeat[lane];
    float* base = (plane == 0) ? (float*)g_xy
                : (plane == 1) ? (float*)g_xz : (float*)g_yz;
    const int2* pr = spr[plane];

    int2 v0 = pr[d0];
    int   cur = v0.x;
    float acc = __int_as_float(v0.y);
#pragma unroll 4
    for (int d = d0 + 1; d < d1; ++d) {
        const int2 v = pr[d];
        const float w = __int_as_float(v.y);
        if (v.x == cur) {
            acc += w;
        } else {
            if (acc > 0.f) {
                float* dst = base + ((size_t)cur << 7) + (lane << 2);
                red4(dst, fv.x * acc, fv.y * acc, fv.z * acc, fv.w * acc);
            }
            cur = v.x;
            acc = w;
        }
    }
    if (acc > 0.f) {
        float* dst = base + ((size_t)cur << 7) + (lane << 2);
        red4(dst, fv.x * acc, fv.y * acc, fv.z * acc, fv.w * acc);
    }
}

// ---- phase 3: smem-free restride [cell][128] -> [128][cells] ----
// Warp handles channel-quad g: lane reads float4 (4 ch of one cell), writes
// 4 coalesced scalar streams. 128 cells per block.
__global__ __launch_bounds__(256)
void restride_kernel(const float* __restrict__ src, float* __restrict__ dst, int cells) {
    const int wrp  = threadIdx.x >> 5;
    const int lane = threadIdx.x & 31;
    const int cellb = blockIdx.x * 128;
    const float4* s4 = (const float4*)src;
#pragma unroll
    for (int gi = 0; gi < 4; ++gi) {
        const int g = wrp + gi * 8;          // channel quad 0..31
#pragma unroll
        for (int cc = 0; cc < 4; ++cc) {
            const int cell = cellb + cc * 32 + lane;
            const float4 v = s4[(size_t)cell * 32 + g];
            dst[(size_t)(4 * g + 0) * cells + cell] = v.x;
            dst[(size_t)(4 * g + 1) * cells + cell] = v.y;
            dst[(size_t)(4 * g + 2) * cells + cell] = v.z;
            dst[(size_t)(4 * g + 3) * cells + cell] = v.w;
        }
    }
}

extern "C" void kernel_launch(void* const* d_in, const int* in_sizes, int n_in,
                              void* d_out, int out_size) {
    const float* img  = (const float*)d_in[0];
    const float* intr = (const float*)d_in[2];
    const float* extr = (const float*)d_in[3];
    const float* Wm   = (const float*)d_in[4];
    const float* bias = (const float*)d_in[5];
    float* out = (float*)d_out;

    void *pxy, *pxz, *pyz;
    cudaGetSymbolAddress(&pxy, g_xy);
    cudaGetSymbolAddress(&pxz, g_xz);
    cudaGetSymbolAddress(&pyz, g_yz);
    cudaMemsetAsync(pxy, 0, sizeof(g_xy));
    cudaMemsetAsync(pxz, 0, sizeof(g_xz));
    cudaMemsetAsync(pyz, 0, sizeof(g_yz));

    dummy_kernel<<<1, 1>>>();
    dummy_kernel<<<1, 1>>>();
    dummy_kernel<<<1, 1>>>();          // prep -> ncu captured launch index 6

    const int prep_smem = (Cc * PB + Cc * WPAD) * (int)sizeof(float);
    cudaFuncSetAttribute(prep_kernel, cudaFuncAttributeMaxDynamicSharedMemorySize, prep_smem);
    prep_kernel<<<NPIX / PB, 256, prep_smem>>>(img, Wm, bias);

    softmax_kernel<<<NPIX / 8, 256>>>();

    scatter_kernel<<<NPIX, 192>>>(intr, extr);

    restride_kernel<<<XY_CELLS / 128, 256>>>((const float*)pxy, out, XY_CELLS);
    restride_kernel<<<XZ_CELLS / 128, 256>>>((const float*)pxz,
                         out + (size_t)Cc * XY_CELLS, XZ_CELLS);
    restride_kernel<<<YZ_CELLS / 128, 256>>>((const float*)pyz,
                         out + (size_t)Cc * (XY_CELLS + XZ_CELLS), YZ_CELLS);
}